// round 15
// baseline (speedup 1.0000x reference)
#include <cuda_runtime.h>
#include <cuda_fp16.h>
#include <math.h>
#include <stdint.h>

// Problem constants
#define BATCH 4
#define SEQ   2048
#define DIM   2048
#define NHEADS 32
#define HDIM  64
#define MTOT  (BATCH * SEQ) // 8192

// Scratch (device globals: allocation-free)
__device__ float  g_h[(size_t)MTOT * DIM];   // input-projection output (f32)
__device__ __half g_s[(size_t)MTOT * DIM];   // rnn states (fp16)
__device__ __half g_x[(size_t)MTOT * DIM];   // x (fp16)
__device__ __half g_w1[(size_t)DIM * DIM];   // w_in (fp16)
__device__ __half g_w2[(size_t)DIM * DIM];   // w_out * norm_weight (fp16)
__device__ float  g_scale[MTOT];             // per-row rmsnorm scale
__device__ int    g_flags[64];               // gemm_in->scan chunk flags

// ---------------------------------------------------------------------------
// helpers
// ---------------------------------------------------------------------------
__device__ __forceinline__ uint32_t smem_u32(const void* p) {
    uint32_t a;
    asm("{ .reg .u64 t; cvta.to.shared.u64 t, %1; cvt.u32.u64 %0, t; }"
        : "=r"(a) : "l"(p));
    return a;
}

#define CP_ASYNC16(dst, src) \
    asm volatile("cp.async.cg.shared.global [%0], [%1], 16;" \
                 :: "r"(dst), "l"(src) : "memory")
#define CP_COMMIT() asm volatile("cp.async.commit_group;" ::: "memory")
#define CP_WAIT(n)  asm volatile("cp.async.wait_group %0;" :: "n"(n) : "memory")

__device__ __forceinline__ void mma_f16(float c[4],
    unsigned a0, unsigned a1, unsigned a2, unsigned a3,
    unsigned b0, unsigned b1)
{
    asm volatile(
        "mma.sync.aligned.m16n8k16.row.col.f32.f16.f16.f32 "
        "{%0,%1,%2,%3}, {%4,%5,%6,%7}, {%8,%9}, {%0,%1,%2,%3};"
        : "+f"(c[0]), "+f"(c[1]), "+f"(c[2]), "+f"(c[3])
        : "r"(a0), "r"(a1), "r"(a2), "r"(a3), "r"(b0), "r"(b1));
}

__device__ __forceinline__ void ldsm_x4(
    unsigned& r0, unsigned& r1, unsigned& r2, unsigned& r3, uint32_t addr)
{
    asm volatile(
        "ldmatrix.sync.aligned.m8n8.x4.shared.b16 {%0,%1,%2,%3}, [%4];"
        : "=r"(r0), "=r"(r1), "=r"(r2), "=r"(r3) : "r"(addr));
}

__device__ __forceinline__ unsigned long long fma_f32x2(
    unsigned long long a, unsigned long long b, unsigned long long c)
{
    unsigned long long d;
    asm("fma.rn.f32x2 %0, %1, %2, %3;" : "=l"(d) : "l"(a), "l"(b), "l"(c));
    return d;
}

__device__ __forceinline__ unsigned long long add_f32x2(
    unsigned long long a, unsigned long long b)
{
    unsigned long long d;
    asm("add.rn.f32x2 %0, %1, %2;" : "=l"(d) : "l"(a), "l"(b));
    return d;
}

__device__ __forceinline__ unsigned long long pack2(float lo, float hi) {
    unsigned long long r;
    asm("mov.b64 %0, {%1, %2};" : "=l"(r) : "f"(lo), "f"(hi));
    return r;
}

__device__ __forceinline__ void unpack2(float& lo, float& hi, unsigned long long v) {
    asm("mov.b64 {%0, %1}, %2;" : "=f"(lo), "=f"(hi) : "l"(v));
}

__device__ __forceinline__ float tanh_fast(float z) {
    float r;
    asm("tanh.approx.f32 %0, %1;" : "=f"(r) : "f"(z));
    return r;
}

__device__ __forceinline__ void wait_flag16(const int* f) {
    int v;
    do {
        asm volatile("ld.acquire.gpu.global.b32 %0, [%1];" : "=r"(v) : "l"(f));
        if (v < 16) __nanosleep(200);
    } while (v < 16);
}

// ---------------------------------------------------------------------------
// FP16 mma.sync GEMM (fp32 accumulate), cp.async 4-stage, 1 sync/chunk,
// 2 CTAs/SM, warp tile 64x64 (128 thr). Optional doneFlags: interleaved
// (tchunk,batch) row mapping + per-y completion signal for scan overlap.
// ---------------------------------------------------------------------------
#define GBM 128
#define GBN 128
#define GBK 32
#define NSTAGE 4
#define SKH 40                   // 80B row stride -> ldsm conflict-free
#define ABYTES (GBM * SKH * 2)   // 10240
#define STGB   (2 * ABYTES)      // 20480 per stage
#define NCHUNK (DIM / GBK)       // 64

__global__ __launch_bounds__(128, 2)
void gemm_h_kernel(const __half* __restrict__ A, const __half* __restrict__ B,
                   const float* __restrict__ bias, float* __restrict__ C,
                   const float* __restrict__ rowScale, int* doneFlags)
{
    extern __shared__ __half smem[];
    const uint32_t sb = smem_u32(smem);

    const int tid  = threadIdx.x;
    const int lane = tid & 31;
    const int wid  = tid >> 5;          // 0..3
    // interleaved mapping when signaling: y = tchunk*4 + b
    const int cRow = doneFlags
        ? (int)((blockIdx.y & 3) * SEQ + (blockIdx.y >> 2) * GBM)
        : (int)(blockIdx.y * GBM);
    const int cCol = blockIdx.x * GBN;

    const int m0  = (wid & 1) * 64;
    const int n0  = (wid >> 1) * 64;
    const int gid = lane >> 2;
    const int tg  = lane & 3;

    const int aRowOff = lane & 15;
    const int aColOff = (lane >> 4) * 8;
    const int bRowOff = ((lane >> 4) & 1) * 8 + (lane & 7);
    const int bColOff = ((lane >> 3) & 1) * 8;
    const uint32_t aOff = sb + (uint32_t)((m0 + aRowOff) * SKH + aColOff) * 2;
    const uint32_t bOff = sb + ABYTES + (uint32_t)((n0 + bRowOff) * SKH + bColOff) * 2;

    float acc[4][8][4];
#pragma unroll
    for (int mf = 0; mf < 4; mf++)
#pragma unroll
        for (int nf = 0; nf < 8; nf++)
#pragma unroll
            for (int i = 0; i < 4; i++) acc[mf][nf][i] = 0.f;

    const int lrow  = tid >> 2;          // 0..31
    const int lslot = tid & 3;
    const __half* aSrc = A + (size_t)(cRow + lrow) * DIM + 8 * lslot;
    const __half* bSrc = B + (size_t)(cCol + lrow) * DIM + 8 * lslot;
    const uint32_t ldst = sb + (uint32_t)(lrow * SKH + 8 * lslot) * 2;

    auto load_chunk = [&](int c, int s) {
        if (c < NCHUNK) {
            const size_t k = (size_t)c * GBK;
            const uint32_t d = ldst + (uint32_t)s * STGB;
#pragma unroll
            for (int i = 0; i < 4; i++) {
                CP_ASYNC16(d + (uint32_t)i * (32 * SKH * 2),
                           aSrc + k + (size_t)i * 32 * DIM);
                CP_ASYNC16(d + ABYTES + (uint32_t)i * (32 * SKH * 2),
                           bSrc + k + (size_t)i * 32 * DIM);
            }
        }
        CP_COMMIT();
    };

    for (int s = 0; s < NSTAGE - 1; s++) load_chunk(s, s);

    for (int c = 0; c < NCHUNK; c++) {
        const int s = c & (NSTAGE - 1);
        CP_WAIT(NSTAGE - 2);
        __syncthreads();
        load_chunk(c + NSTAGE - 1, (c + NSTAGE - 1) & (NSTAGE - 1));

        const uint32_t aS = aOff + (uint32_t)s * STGB;
        const uint32_t bS = bOff + (uint32_t)s * STGB;

#pragma unroll
        for (int ks = 0; ks < 2; ks++) {
            const uint32_t kb = 32 * ks;
            unsigned a[4][4], b[8][2];
#pragma unroll
            for (int mf = 0; mf < 4; mf++)
                ldsm_x4(a[mf][0], a[mf][1], a[mf][2], a[mf][3],
                        aS + kb + (uint32_t)mf * (16 * SKH * 2));
#pragma unroll
            for (int p = 0; p < 4; p++)
                ldsm_x4(b[2*p][0], b[2*p][1], b[2*p+1][0], b[2*p+1][1],
                        bS + kb + (uint32_t)p * (16 * SKH * 2));
#pragma unroll
            for (int mf = 0; mf < 4; mf++)
#pragma unroll
                for (int nf = 0; nf < 8; nf++)
                    mma_f16(acc[mf][nf], a[mf][0], a[mf][1], a[mf][2], a[mf][3],
                            b[nf][0], b[nf][1]);
        }
    }

#pragma unroll
    for (int mf = 0; mf < 4; mf++) {
        const int row = cRow + m0 + 16 * mf + gid;
        const float rs0 = rowScale ? rowScale[row] : 1.f;
        const float rs1 = rowScale ? rowScale[row + 8] : 1.f;
#pragma unroll
        for (int nf = 0; nf < 8; nf++) {
            const int col = cCol + n0 + 8 * nf + 2 * tg;
            float b0 = 0.f, b1 = 0.f;
            if (bias) { b0 = bias[col]; b1 = bias[col + 1]; }
            float2 v0 = make_float2(acc[mf][nf][0] * rs0 + b0, acc[mf][nf][1] * rs0 + b1);
            float2 v1 = make_float2(acc[mf][nf][2] * rs1 + b0, acc[mf][nf][3] * rs1 + b1);
            *(float2*)(C + (size_t)row * DIM + col) = v0;
            *(float2*)(C + (size_t)(row + 8) * DIM + col) = v1;
        }
    }

    if (doneFlags) {
        __threadfence();
        __syncthreads();
        if (tid == 0) atomicAdd(doneFlags + blockIdx.y, 1);
    }
}

// ---------------------------------------------------------------------------
// f32 -> fp16 conversions (8 elems/thread); colscale folds norm_weight
// ---------------------------------------------------------------------------
__global__ __launch_bounds__(256) void cvt_h_kernel(
    const float* __restrict__ in, __half* __restrict__ out)
{
    const size_t i = ((size_t)blockIdx.x * 256 + threadIdx.x) * 8;
    const float4 v0 = *(const float4*)(in + i);
    const float4 v1 = *(const float4*)(in + i + 4);
    __half2 h[4];
    h[0] = __floats2half2_rn(v0.x, v0.y);
    h[1] = __floats2half2_rn(v0.z, v0.w);
    h[2] = __floats2half2_rn(v1.x, v1.y);
    h[3] = __floats2half2_rn(v1.z, v1.w);
    *(uint4*)(out + i) = *(const uint4*)h;
}

__global__ __launch_bounds__(256) void cvt_h_colscale_kernel(
    const float* __restrict__ in, const float* __restrict__ colw,
    __half* __restrict__ out)
{
    const size_t i = ((size_t)blockIdx.x * 256 + threadIdx.x) * 8;
    const int c = (int)(i & (DIM - 1));
    const float4 v0 = *(const float4*)(in + i);
    const float4 v1 = *(const float4*)(in + i + 4);
    const float4 g0 = *(const float4*)(colw + c);
    const float4 g1 = *(const float4*)(colw + c + 4);
    __half2 h[4];
    h[0] = __floats2half2_rn(v0.x * g0.x, v0.y * g0.y);
    h[1] = __floats2half2_rn(v0.z * g0.z, v0.w * g0.w);
    h[2] = __floats2half2_rn(v1.x * g1.x, v1.y * g1.y);
    h[3] = __floats2half2_rn(v1.z * g1.z, v1.w * g1.w);
    *(uint4*)(out + i) = *(const uint4*)h;
}

// ---------------------------------------------------------------------------
// RNN scan: 64 threads/CTA, one output/thread (proven R13 core), CHUNKED
// with spin-wait on gemm_in completion flags so it overlaps gemm_in.
// Chunk = 128 timesteps; waits one chunk ahead of the prefetch window.
// ---------------------------------------------------------------------------
__global__ __launch_bounds__(64) void rnn_scan_kernel(
    const float* __restrict__ state_weight)
{
    const int b = blockIdx.x >> 5;
    const int n = blockIdx.x & 31;
    const int j = threadIdx.x;           // 0..63, owns output j

    __shared__ float s_sh[2][HDIM];

    unsigned long long Wp[32];
    const float* Wn = state_weight + (size_t)n * HDIM * HDIM;
#pragma unroll
    for (int i = 0; i < 32; i++)
        Wp[i] = pack2(Wn[(2 * i) * HDIM + j], Wn[(2 * i + 1) * HDIM + j]);

    s_sh[0][j] = 0.f;
    __syncthreads();

    const size_t base = ((size_t)b * SEQ) * DIM + n * HDIM + j;
    const float* gin = g_h + base;
    __half* gout = g_s + base;

    // wait for chunk 0 before initial prefetch
    wait_flag16(&g_flags[0 * 4 + b]);

    float pf[8];
#pragma unroll
    for (int u = 0; u < 8; u++) pf[u] = __ldg(gin + (size_t)u * DIM);
    const float* gpf = gin + 8 * DIM;

    int cur = 0;

#define SCAN_STEP(XT, T)                                                     \
    do {                                                                     \
        const float4* sp = (const float4*)s_sh[cur];                         \
        unsigned long long acc0, acc1, acc2, acc3;                           \
        {                                                                    \
            const float4 v0 = sp[0], v1 = sp[1], v2 = sp[2], v3 = sp[3];     \
            const unsigned long long z = pack2(0.f, 0.f);                    \
            acc0 = fma_f32x2(pack2(v0.x, v0.y), Wp[0], z);                   \
            acc1 = fma_f32x2(pack2(v0.z, v0.w), Wp[1], z);                   \
            acc2 = fma_f32x2(pack2(v1.x, v1.y), Wp[2], z);                   \
            acc3 = fma_f32x2(pack2(v1.z, v1.w), Wp[3], z);                   \
            acc0 = fma_f32x2(pack2(v2.x, v2.y), Wp[4], acc0);                \
            acc1 = fma_f32x2(pack2(v2.z, v2.w), Wp[5], acc1);                \
            acc2 = fma_f32x2(pack2(v3.x, v3.y), Wp[6], acc2);                \
            acc3 = fma_f32x2(pack2(v3.z, v3.w), Wp[7], acc3);                \
        }                                                                    \
        _Pragma("unroll")                                                    \
        for (int q = 4; q < 16; q += 4) {                                    \
            const float4 v0 = sp[q], v1 = sp[q+1], v2 = sp[q+2], v3 = sp[q+3];\
            acc0 = fma_f32x2(pack2(v0.x, v0.y), Wp[2*q + 0], acc0);          \
            acc1 = fma_f32x2(pack2(v0.z, v0.w), Wp[2*q + 1], acc1);          \
            acc2 = fma_f32x2(pack2(v1.x, v1.y), Wp[2*q + 2], acc2);          \
            acc3 = fma_f32x2(pack2(v1.z, v1.w), Wp[2*q + 3], acc3);          \
            acc0 = fma_f32x2(pack2(v2.x, v2.y), Wp[2*q + 4], acc0);          \
            acc1 = fma_f32x2(pack2(v2.z, v2.w), Wp[2*q + 5], acc1);          \
            acc2 = fma_f32x2(pack2(v3.x, v3.y), Wp[2*q + 6], acc2);          \
            acc3 = fma_f32x2(pack2(v3.z, v3.w), Wp[2*q + 7], acc3);          \
        }                                                                    \
        unsigned long long sT = add_f32x2(add_f32x2(acc0, acc1),             \
                                          add_f32x2(acc2, acc3));            \
        float lo, hi;                                                        \
        unpack2(lo, hi, sT);                                                 \
        const float sv = tanh_fast(lo + hi + (XT));                          \
        s_sh[cur ^ 1][j] = sv;                                               \
        gout[(size_t)(T) * DIM] = __float2half_rn(sv);                       \
        cur ^= 1;                                                            \
        __syncthreads();                                                     \
    } while (0)

    for (int c = 0; c < 16; c++) {
        // cover this chunk's prefetch reach into chunk c+1
        const int cw = (c + 1 < 16) ? (c + 1) : 15;
        wait_flag16(&g_flags[cw * 4 + b]);
        const int t0 = c * 128;
        for (int t = t0; t < t0 + 128; t += 8) {
#pragma unroll
            for (int u = 0; u < 8; u++) {
                SCAN_STEP(pf[u], t + u);
                pf[u] = (t + 8 + u < SEQ) ? __ldg(gpf + (size_t)u * DIM) : 0.f;
            }
            gpf += 8 * DIM;
        }
    }
#undef SCAN_STEP
}

// ---------------------------------------------------------------------------
// Row scale: g_scale[row] = rsqrt(mean(states^2) + eps), reading fp16 states
// ---------------------------------------------------------------------------
__global__ __launch_bounds__(256) void row_scale_kernel()
{
    const int row = blockIdx.x;
    const __half* p = g_s + (size_t)row * DIM;
    const int t = threadIdx.x;

    const uint4 u = ((const uint4*)p)[t];
    const __half2* hp = (const __half2*)&u;
    float ss = 0.f;
#pragma unroll
    for (int i = 0; i < 4; i++) {
        float2 f = __half22float2(hp[i]);
        ss += f.x * f.x + f.y * f.y;
    }

#pragma unroll
    for (int off = 16; off > 0; off >>= 1)
        ss += __shfl_xor_sync(0xFFFFFFFFu, ss, off);

    __shared__ float red[8];
    const int warp = t >> 5;
    const int lane = t & 31;
    if (lane == 0) red[warp] = ss;
    __syncthreads();
    if (warp == 0) {
        float v = (lane < 8) ? red[lane] : 0.f;
#pragma unroll
        for (int off = 4; off > 0; off >>= 1)
            v += __shfl_xor_sync(0xFFFFFFFFu, v, off);
        if (lane == 0) g_scale[row] = rsqrtf(v * (1.0f / DIM) + 1e-6f);
    }
}

// ---------------------------------------------------------------------------
// Launch: gemm_in forked to a non-blocking stream; scan co-runs on the main
// stream spin-waiting on per-chunk flags. cvt_w2 hides under gemm_in.
// ---------------------------------------------------------------------------
extern "C" void kernel_launch(void* const* d_in, const int* in_sizes, int n_in,
                              void* d_out, int out_size)
{
    const float* x            = (const float*)d_in[0];
    const float* w_in         = (const float*)d_in[1];
    const float* b_in         = (const float*)d_in[2];
    const float* state_weight = (const float*)d_in[3];
    const float* norm_weight  = (const float*)d_in[4];
    const float* w_out        = (const float*)d_in[5];
    float* out = (float*)d_out;

    __half *gx, *gw1, *gw2, *gs;
    float *gh, *gscale;
    int *gflags;
    cudaGetSymbolAddress((void**)&gx,  g_x);
    cudaGetSymbolAddress((void**)&gw1, g_w1);
    cudaGetSymbolAddress((void**)&gw2, g_w2);
    cudaGetSymbolAddress((void**)&gh,  g_h);
    cudaGetSymbolAddress((void**)&gs,  g_s);
    cudaGetSymbolAddress((void**)&gscale, g_scale);
    cudaGetSymbolAddress((void**)&gflags, g_flags);

    static cudaStream_t s2 = nullptr;
    static cudaEvent_t e0 = nullptr, e1 = nullptr;
    if (!s2) {
        cudaStreamCreateWithFlags(&s2, cudaStreamNonBlocking);
        cudaEventCreateWithFlags(&e0, cudaEventDisableTiming);
        cudaEventCreateWithFlags(&e1, cudaEventDisableTiming);
    }

    const int SMEM_TOTAL = STGB * NSTAGE;   // 81920
    cudaFuncSetAttribute(gemm_h_kernel,
                         cudaFuncAttributeMaxDynamicSharedMemorySize, SMEM_TOTAL);

    dim3 ggrid(DIM / GBN, MTOT / GBM);   // (16, 64)

    // reset flags, prep gemm_in operands on main stream
    cudaMemsetAsync(gflags, 0, 64 * sizeof(int), 0);
    cvt_h_kernel<<<(MTOT * DIM) / 2048, 256>>>(x, gx);
    cvt_h_kernel<<<(DIM * DIM) / 2048, 256>>>(w_in, gw1);

    // fork: gemm_in on s2 (signals chunk flags)
    cudaEventRecord(e0, 0);
    cudaStreamWaitEvent(s2, e0, 0);
    gemm_h_kernel<<<ggrid, 128, SMEM_TOTAL, s2>>>(gx, gw1, b_in, gh, nullptr, gflags);
    cudaEventRecord(e1, s2);

    // main stream: w_out prep + scan overlap with gemm_in
    cvt_h_colscale_kernel<<<(DIM * DIM) / 2048, 256>>>(w_out, norm_weight, gw2);
    rnn_scan_kernel<<<BATCH * NHEADS, 64>>>(state_weight);

    // join, then norm scale + output GEMM
    cudaStreamWaitEvent(0, e1, 0);
    row_scale_kernel<<<MTOT, 256>>>();
    gemm_h_kernel<<<ggrid, 128, SMEM_TOTAL>>>(gs, gw2, nullptr, out, gscale, nullptr);
}

// round 16
// speedup vs baseline: 1.0583x; 1.0583x over previous
#include <cuda_runtime.h>
#include <cuda_fp16.h>
#include <math.h>
#include <stdint.h>

// Problem constants
#define BATCH 4
#define SEQ   2048
#define DIM   2048
#define NHEADS 32
#define HDIM  64
#define MTOT  (BATCH * SEQ) // 8192

// Scratch (device globals: allocation-free)
__device__ float  g_h[(size_t)MTOT * DIM];   // input-projection output (f32)
__device__ __half g_s[(size_t)MTOT * DIM];   // rnn states (fp16)
__device__ __half g_x[(size_t)MTOT * DIM];   // x (fp16)
__device__ __half g_w1[(size_t)DIM * DIM];   // w_in (fp16)
__device__ __half g_w2[(size_t)DIM * DIM];   // w_out * norm_weight (fp16)
__device__ float  g_scale[MTOT];             // per-row rmsnorm scale

// ---------------------------------------------------------------------------
// helpers
// ---------------------------------------------------------------------------
__device__ __forceinline__ uint32_t smem_u32(const void* p) {
    uint32_t a;
    asm("{ .reg .u64 t; cvta.to.shared.u64 t, %1; cvt.u32.u64 %0, t; }"
        : "=r"(a) : "l"(p));
    return a;
}

#define CP_ASYNC16(dst, src) \
    asm volatile("cp.async.cg.shared.global [%0], [%1], 16;" \
                 :: "r"(dst), "l"(src) : "memory")
#define CP_COMMIT() asm volatile("cp.async.commit_group;" ::: "memory")
#define CP_WAIT(n)  asm volatile("cp.async.wait_group %0;" :: "n"(n) : "memory")

__device__ __forceinline__ void mma_f16(float c[4],
    unsigned a0, unsigned a1, unsigned a2, unsigned a3,
    unsigned b0, unsigned b1)
{
    asm volatile(
        "mma.sync.aligned.m16n8k16.row.col.f32.f16.f16.f32 "
        "{%0,%1,%2,%3}, {%4,%5,%6,%7}, {%8,%9}, {%0,%1,%2,%3};"
        : "+f"(c[0]), "+f"(c[1]), "+f"(c[2]), "+f"(c[3])
        : "r"(a0), "r"(a1), "r"(a2), "r"(a3), "r"(b0), "r"(b1));
}

__device__ __forceinline__ void ldsm_x4(
    unsigned& r0, unsigned& r1, unsigned& r2, unsigned& r3, uint32_t addr)
{
    asm volatile(
        "ldmatrix.sync.aligned.m8n8.x4.shared.b16 {%0,%1,%2,%3}, [%4];"
        : "=r"(r0), "=r"(r1), "=r"(r2), "=r"(r3) : "r"(addr));
}

__device__ __forceinline__ unsigned long long fma_f32x2(
    unsigned long long a, unsigned long long b, unsigned long long c)
{
    unsigned long long d;
    asm("fma.rn.f32x2 %0, %1, %2, %3;" : "=l"(d) : "l"(a), "l"(b), "l"(c));
    return d;
}

__device__ __forceinline__ unsigned long long add_f32x2(
    unsigned long long a, unsigned long long b)
{
    unsigned long long d;
    asm("add.rn.f32x2 %0, %1, %2;" : "=l"(d) : "l"(a), "l"(b));
    return d;
}

__device__ __forceinline__ unsigned long long pack2(float lo, float hi) {
    unsigned long long r;
    asm("mov.b64 %0, {%1, %2};" : "=l"(r) : "f"(lo), "f"(hi));
    return r;
}

__device__ __forceinline__ void unpack2(float& lo, float& hi, unsigned long long v) {
    asm("mov.b64 {%0, %1}, %2;" : "=f"(lo), "=f"(hi) : "l"(v));
}

__device__ __forceinline__ float tanh_fast(float z) {
    float r;
    asm("tanh.approx.f32 %0, %1;" : "=f"(r) : "f"(z));
    return r;
}

// ---------------------------------------------------------------------------
// FP16 mma.sync GEMM (fp32 accumulate), cp.async 4-stage, 1 sync/chunk,
// 2 CTAs/SM, warp tile 64x64 (128 thr). Both k-steps' ldsm issued up-front
// (12 back-to-back LDSM, max LDS MLP) before the 64 HMMA of the chunk.
// ---------------------------------------------------------------------------
#define GBM 128
#define GBN 128
#define GBK 32
#define NSTAGE 4
#define SKH 40                   // 80B row stride -> ldsm conflict-free
#define ABYTES (GBM * SKH * 2)   // 10240
#define STGB   (2 * ABYTES)      // 20480 per stage
#define NCHUNK (DIM / GBK)       // 64

#define LD_FRAGS(aArr, bArr, aS, bS, kb)                                     \
    do {                                                                     \
        _Pragma("unroll")                                                    \
        for (int mf = 0; mf < 4; mf++)                                       \
            ldsm_x4((aArr)[mf][0], (aArr)[mf][1], (aArr)[mf][2], (aArr)[mf][3],\
                    (aS) + (kb) + (uint32_t)mf * (16 * SKH * 2));            \
        _Pragma("unroll")                                                    \
        for (int p = 0; p < 4; p++)                                          \
            ldsm_x4((bArr)[2*p][0], (bArr)[2*p][1],                          \
                    (bArr)[2*p+1][0], (bArr)[2*p+1][1],                      \
                    (bS) + (kb) + (uint32_t)p * (16 * SKH * 2));             \
    } while (0)

#define MMA_BLOCK(aArr, bArr)                                                \
    do {                                                                     \
        _Pragma("unroll")                                                    \
        for (int mf = 0; mf < 4; mf++)                                       \
            _Pragma("unroll")                                                \
            for (int nf = 0; nf < 8; nf++)                                   \
                mma_f16(acc[mf][nf], (aArr)[mf][0], (aArr)[mf][1],           \
                        (aArr)[mf][2], (aArr)[mf][3],                        \
                        (bArr)[nf][0], (bArr)[nf][1]);                       \
    } while (0)

__global__ __launch_bounds__(128, 2)
void gemm_h_kernel(const __half* __restrict__ A, const __half* __restrict__ B,
                   const float* __restrict__ bias, float* __restrict__ C,
                   const float* __restrict__ rowScale)
{
    extern __shared__ __half smem[];
    const uint32_t sb = smem_u32(smem);

    const int tid  = threadIdx.x;
    const int lane = tid & 31;
    const int wid  = tid >> 5;          // 0..3
    const int cRow = blockIdx.y * GBM;
    const int cCol = blockIdx.x * GBN;

    const int m0  = (wid & 1) * 64;
    const int n0  = (wid >> 1) * 64;
    const int gid = lane >> 2;
    const int tg  = lane & 3;

    const int aRowOff = lane & 15;
    const int aColOff = (lane >> 4) * 8;
    const int bRowOff = ((lane >> 4) & 1) * 8 + (lane & 7);
    const int bColOff = ((lane >> 3) & 1) * 8;
    const uint32_t aOff = sb + (uint32_t)((m0 + aRowOff) * SKH + aColOff) * 2;
    const uint32_t bOff = sb + ABYTES + (uint32_t)((n0 + bRowOff) * SKH + bColOff) * 2;

    float acc[4][8][4];
#pragma unroll
    for (int mf = 0; mf < 4; mf++)
#pragma unroll
        for (int nf = 0; nf < 8; nf++)
#pragma unroll
            for (int i = 0; i < 4; i++) acc[mf][nf][i] = 0.f;

    const int lrow  = tid >> 2;          // 0..31
    const int lslot = tid & 3;
    const __half* aSrc = A + (size_t)(cRow + lrow) * DIM + 8 * lslot;
    const __half* bSrc = B + (size_t)(cCol + lrow) * DIM + 8 * lslot;
    const uint32_t ldst = sb + (uint32_t)(lrow * SKH + 8 * lslot) * 2;

    auto load_chunk = [&](int c, int s) {
        if (c < NCHUNK) {
            const size_t k = (size_t)c * GBK;
            const uint32_t d = ldst + (uint32_t)s * STGB;
#pragma unroll
            for (int i = 0; i < 4; i++) {
                CP_ASYNC16(d + (uint32_t)i * (32 * SKH * 2),
                           aSrc + k + (size_t)i * 32 * DIM);
                CP_ASYNC16(d + ABYTES + (uint32_t)i * (32 * SKH * 2),
                           bSrc + k + (size_t)i * 32 * DIM);
            }
        }
        CP_COMMIT();
    };

    for (int s = 0; s < NSTAGE - 1; s++) load_chunk(s, s);

    for (int c = 0; c < NCHUNK; c++) {
        const int s = c & (NSTAGE - 1);
        CP_WAIT(NSTAGE - 2);
        __syncthreads();
        load_chunk(c + NSTAGE - 1, (c + NSTAGE - 1) & (NSTAGE - 1));

        const uint32_t aS = aOff + (uint32_t)s * STGB;
        const uint32_t bS = bOff + (uint32_t)s * STGB;

        unsigned a0[4][4], b0[8][2], a1[4][4], b1[8][2];
        LD_FRAGS(a0, b0, aS, bS, 0u);
        LD_FRAGS(a1, b1, aS, bS, 32u);
        MMA_BLOCK(a0, b0);
        MMA_BLOCK(a1, b1);
    }

#pragma unroll
    for (int mf = 0; mf < 4; mf++) {
        const int row = cRow + m0 + 16 * mf + gid;
        const float rs0 = rowScale ? rowScale[row] : 1.f;
        const float rs1 = rowScale ? rowScale[row + 8] : 1.f;
#pragma unroll
        for (int nf = 0; nf < 8; nf++) {
            const int col = cCol + n0 + 8 * nf + 2 * tg;
            float b0v = 0.f, b1v = 0.f;
            if (bias) { b0v = bias[col]; b1v = bias[col + 1]; }
            float2 v0 = make_float2(acc[mf][nf][0] * rs0 + b0v, acc[mf][nf][1] * rs0 + b1v);
            float2 v1 = make_float2(acc[mf][nf][2] * rs1 + b0v, acc[mf][nf][3] * rs1 + b1v);
            *(float2*)(C + (size_t)row * DIM + col) = v0;
            *(float2*)(C + (size_t)(row + 8) * DIM + col) = v1;
        }
    }
}

// ---------------------------------------------------------------------------
// f32 -> fp16 conversions (8 elems/thread); colscale folds norm_weight
// ---------------------------------------------------------------------------
__global__ __launch_bounds__(256) void cvt_h_kernel(
    const float* __restrict__ in, __half* __restrict__ out)
{
    const size_t i = ((size_t)blockIdx.x * 256 + threadIdx.x) * 8;
    const float4 v0 = *(const float4*)(in + i);
    const float4 v1 = *(const float4*)(in + i + 4);
    __half2 h[4];
    h[0] = __floats2half2_rn(v0.x, v0.y);
    h[1] = __floats2half2_rn(v0.z, v0.w);
    h[2] = __floats2half2_rn(v1.x, v1.y);
    h[3] = __floats2half2_rn(v1.z, v1.w);
    *(uint4*)(out + i) = *(const uint4*)h;
}

__global__ __launch_bounds__(256) void cvt_h_colscale_kernel(
    const float* __restrict__ in, const float* __restrict__ colw,
    __half* __restrict__ out)
{
    const size_t i = ((size_t)blockIdx.x * 256 + threadIdx.x) * 8;
    const int c = (int)(i & (DIM - 1));
    const float4 v0 = *(const float4*)(in + i);
    const float4 v1 = *(const float4*)(in + i + 4);
    const float4 g0 = *(const float4*)(colw + c);
    const float4 g1 = *(const float4*)(colw + c + 4);
    __half2 h[4];
    h[0] = __floats2half2_rn(v0.x * g0.x, v0.y * g0.y);
    h[1] = __floats2half2_rn(v0.z * g0.z, v0.w * g0.w);
    h[2] = __floats2half2_rn(v1.x * g1.x, v1.y * g1.y);
    h[3] = __floats2half2_rn(v1.z * g1.z, v1.w * g1.w);
    *(uint4*)(out + i) = *(const uint4*)h;
}

// ---------------------------------------------------------------------------
// RNN scan: 64 threads/CTA, ONE output per thread (proven best, R13).
// Broadcast LDS.128 state reads, f32x2 FMAs in 4 chains, tanh.approx,
// single writer, one 2-warp __syncthreads per step, depth-8 prefetch.
// ---------------------------------------------------------------------------
__global__ __launch_bounds__(64) void rnn_scan_kernel(
    const float* __restrict__ state_weight)
{
    const int b = blockIdx.x >> 5;
    const int n = blockIdx.x & 31;
    const int j = threadIdx.x;           // 0..63, owns output j

    __shared__ float s_sh[2][HDIM];

    unsigned long long Wp[32];
    const float* Wn = state_weight + (size_t)n * HDIM * HDIM;
#pragma unroll
    for (int i = 0; i < 32; i++)
        Wp[i] = pack2(Wn[(2 * i) * HDIM + j], Wn[(2 * i + 1) * HDIM + j]);

    s_sh[0][j] = 0.f;
    __syncthreads();

    const size_t base = ((size_t)b * SEQ) * DIM + n * HDIM + j;
    const float* gin = g_h + base;
    __half* gout = g_s + base;

    float pf[8];
#pragma unroll
    for (int u = 0; u < 8; u++) pf[u] = __ldg(gin + (size_t)u * DIM);
    const float* gpf = gin + 8 * DIM;

    int cur = 0;

#define SCAN_STEP(XT, T)                                                     \
    do {                                                                     \
        const float4* sp = (const float4*)s_sh[cur];                         \
        unsigned long long acc0, acc1, acc2, acc3;                           \
        {                                                                    \
            const float4 v0 = sp[0], v1 = sp[1], v2 = sp[2], v3 = sp[3];     \
            const unsigned long long z = pack2(0.f, 0.f);                    \
            acc0 = fma_f32x2(pack2(v0.x, v0.y), Wp[0], z);                   \
            acc1 = fma_f32x2(pack2(v0.z, v0.w), Wp[1], z);                   \
            acc2 = fma_f32x2(pack2(v1.x, v1.y), Wp[2], z);                   \
            acc3 = fma_f32x2(pack2(v1.z, v1.w), Wp[3], z);                   \
            acc0 = fma_f32x2(pack2(v2.x, v2.y), Wp[4], acc0);                \
            acc1 = fma_f32x2(pack2(v2.z, v2.w), Wp[5], acc1);                \
            acc2 = fma_f32x2(pack2(v3.x, v3.y), Wp[6], acc2);                \
            acc3 = fma_f32x2(pack2(v3.z, v3.w), Wp[7], acc3);                \
        }                                                                    \
        _Pragma("unroll")                                                    \
        for (int q = 4; q < 16; q += 4) {                                    \
            const float4 v0 = sp[q], v1 = sp[q+1], v2 = sp[q+2], v3 = sp[q+3];\
            acc0 = fma_f32x2(pack2(v0.x, v0.y), Wp[2*q + 0], acc0);          \
            acc1 = fma_f32x2(pack2(v0.z, v0.w), Wp[2*q + 1], acc1);          \
            acc2 = fma_f32x2(pack2(v1.x, v1.y), Wp[2*q + 2], acc2);          \
            acc3 = fma_f32x2(pack2(v1.z, v1.w), Wp[2*q + 3], acc3);          \
            acc0 = fma_f32x2(pack2(v2.x, v2.y), Wp[2*q + 4], acc0);          \
            acc1 = fma_f32x2(pack2(v2.z, v2.w), Wp[2*q + 5], acc1);          \
            acc2 = fma_f32x2(pack2(v3.x, v3.y), Wp[2*q + 6], acc2);          \
            acc3 = fma_f32x2(pack2(v3.z, v3.w), Wp[2*q + 7], acc3);          \
        }                                                                    \
        unsigned long long sT = add_f32x2(add_f32x2(acc0, acc1),             \
                                          add_f32x2(acc2, acc3));            \
        float lo, hi;                                                        \
        unpack2(lo, hi, sT);                                                 \
        const float sv = tanh_fast(lo + hi + (XT));                          \
        s_sh[cur ^ 1][j] = sv;                                               \
        gout[(size_t)(T) * DIM] = __float2half_rn(sv);                       \
        cur ^= 1;                                                            \
        __syncthreads();                                                     \
    } while (0)

    for (int t = 0; t < SEQ; t += 8) {
#pragma unroll
        for (int u = 0; u < 8; u++) {
            SCAN_STEP(pf[u], t + u);
            pf[u] = (t + 8 + u < SEQ) ? __ldg(gpf + (size_t)u * DIM) : 0.f;
        }
        gpf += 8 * DIM;
    }
#undef SCAN_STEP
}

// ---------------------------------------------------------------------------
// Row scale: g_scale[row] = rsqrt(mean(states^2) + eps), reading fp16 states
// ---------------------------------------------------------------------------
__global__ __launch_bounds__(256) void row_scale_kernel()
{
    const int row = blockIdx.x;
    const __half* p = g_s + (size_t)row * DIM;
    const int t = threadIdx.x;

    const uint4 u = ((const uint4*)p)[t];
    const __half2* hp = (const __half2*)&u;
    float ss = 0.f;
#pragma unroll
    for (int i = 0; i < 4; i++) {
        float2 f = __half22float2(hp[i]);
        ss += f.x * f.x + f.y * f.y;
    }

#pragma unroll
    for (int off = 16; off > 0; off >>= 1)
        ss += __shfl_xor_sync(0xFFFFFFFFu, ss, off);

    __shared__ float red[8];
    const int warp = t >> 5;
    const int lane = t & 31;
    if (lane == 0) red[warp] = ss;
    __syncthreads();
    if (warp == 0) {
        float v = (lane < 8) ? red[lane] : 0.f;
#pragma unroll
        for (int off = 4; off > 0; off >>= 1)
            v += __shfl_xor_sync(0xFFFFFFFFu, v, off);
        if (lane == 0) g_scale[row] = rsqrtf(v * (1.0f / DIM) + 1e-6f);
    }
}

// ---------------------------------------------------------------------------
// Launch (serial schedule — proven fastest; overlap attempt regressed)
// ---------------------------------------------------------------------------
extern "C" void kernel_launch(void* const* d_in, const int* in_sizes, int n_in,
                              void* d_out, int out_size)
{
    const float* x            = (const float*)d_in[0];
    const float* w_in         = (const float*)d_in[1];
    const float* b_in         = (const float*)d_in[2];
    const float* state_weight = (const float*)d_in[3];
    const float* norm_weight  = (const float*)d_in[4];
    const float* w_out        = (const float*)d_in[5];
    float* out = (float*)d_out;

    __half *gx, *gw1, *gw2, *gs;
    float *gh, *gscale;
    cudaGetSymbolAddress((void**)&gx,  g_x);
    cudaGetSymbolAddress((void**)&gw1, g_w1);
    cudaGetSymbolAddress((void**)&gw2, g_w2);
    cudaGetSymbolAddress((void**)&gh,  g_h);
    cudaGetSymbolAddress((void**)&gs,  g_s);
    cudaGetSymbolAddress((void**)&gscale, g_scale);

    const int SMEM_TOTAL = STGB * NSTAGE;   // 81920
    cudaFuncSetAttribute(gemm_h_kernel,
                         cudaFuncAttributeMaxDynamicSharedMemorySize, SMEM_TOTAL);

    // fp16 operand prep (norm_weight folded into w_out)
    cvt_h_kernel<<<(MTOT * DIM) / 2048, 256>>>(x, gx);
    cvt_h_kernel<<<(DIM * DIM) / 2048, 256>>>(w_in, gw1);
    cvt_h_colscale_kernel<<<(DIM * DIM) / 2048, 256>>>(w_out, norm_weight, gw2);

    dim3 ggrid(DIM / GBN, MTOT / GBM);   // (16, 64)

    gemm_h_kernel<<<ggrid, 128, SMEM_TOTAL>>>(gx, gw1, b_in, gh, nullptr);
    rnn_scan_kernel<<<BATCH * NHEADS, 64>>>(state_weight);
    row_scale_kernel<<<MTOT, 256>>>();
    gemm_h_kernel<<<ggrid, 128, SMEM_TOTAL>>>(gs, gw2, nullptr, out, gscale);
}